// round 2
// baseline (speedup 1.0000x reference)
#include <cuda_runtime.h>
#include <math.h>

#define T 8192
#define D 4096
#define E 8
#define KSEL 2
#define SLOTS (T * KSEL)

// Output layout (float32, concatenated in reference-return order)
#define OFF_XG  0
#define OFF_CNT 67108864ll   // 16384*4096
#define OFF_IDX 67108872ll
#define OFF_SC  67125256ll

// Scratch (no allocations allowed -> __device__ globals)
__device__ int   g_exp[SLOTS];
__device__ float g_prob[SLOTS];
__device__ int   g_pos[SLOTS];

__device__ __forceinline__ float dot4(float4 a, float4 b) {
    return a.x * b.x + a.y * b.y + a.z * b.z + a.w * b.w;
}

// ---------------------------------------------------------------------------
// Kernel A: router scores + top-2 + softmax.
// 2 tokens per warp, inner loop unrolled x2 -> 4 independent x-loads in
// flight per warp-iteration. grid = T/16 = 512 blocks of 256 threads
// (4096 warps = 27.7/SM).
// ---------------------------------------------------------------------------
__global__ void __launch_bounds__(256) router_scores_kernel(
    const float* __restrict__ x, const float* __restrict__ W)
{
    const int warp = blockIdx.x * (blockDim.x >> 5) + (threadIdx.x >> 5);
    const int lane = threadIdx.x & 31;
    const int t0 = warp * 2;
    if (t0 >= T) return;

    float acc[2][E];
#pragma unroll
    for (int j = 0; j < 2; j++)
#pragma unroll
        for (int e = 0; e < E; e++) acc[j][e] = 0.f;

    const float4* __restrict__ x4 = (const float4*)x;
    const float4* __restrict__ w4 = (const float4*)W;
    const int rs = D / 4;  // 1024 float4 per row

    const float4* __restrict__ xr0 = x4 + (size_t)t0 * rs;
    const float4* __restrict__ xr1 = x4 + (size_t)(t0 + 1) * rs;

#pragma unroll 2
    for (int i = lane; i < rs; i += 64) {
        // 4 independent global loads up front (MLP)
        float4 xa0 = xr0[i];
        float4 xa1 = xr0[i + 32];
        float4 xb0 = xr1[i];
        float4 xb1 = xr1[i + 32];
#pragma unroll
        for (int e = 0; e < E; e++) {
            float4 w0 = w4[e * rs + i];
            float4 w1 = w4[e * rs + i + 32];
            acc[0][e] += dot4(xa0, w0) + dot4(xa1, w1);
            acc[1][e] += dot4(xb0, w0) + dot4(xb1, w1);
        }
    }

    // warp tree-reduce
#pragma unroll
    for (int off = 16; off > 0; off >>= 1) {
#pragma unroll
        for (int j = 0; j < 2; j++)
#pragma unroll
            for (int e = 0; e < E; e++)
                acc[j][e] += __shfl_xor_sync(0xffffffffu, acc[j][e], off);
    }

    if (lane < 2) {
        const int t = t0 + lane;
        // stable top-2 (first occurrence wins ties, matching jax.lax.top_k)
        float b0 = -3.4e38f, b1 = -3.4e38f;
        int i0 = 0, i1 = 0;
#pragma unroll
        for (int e = 0; e < E; e++) {
            float s = acc[lane][e];
            if (s > b0) { b1 = b0; i1 = i0; b0 = s; i0 = e; }
            else if (s > b1) { b1 = s; i1 = e; }
        }
        float ex = expf(b1 - b0);
        float inv = 1.f / (1.f + ex);
        g_exp[2 * t]     = i0;
        g_exp[2 * t + 1] = i1;
        g_prob[2 * t]     = inv;
        g_prob[2 * t + 1] = ex * inv;
    }
}

// ---------------------------------------------------------------------------
// Kernel B: deterministic per-expert stable ranking.
// Single block, 1024 threads = 32 warps. Per-thread 16-slot histograms,
// warp-level shuffle scan (5 steps), one cross-warp scan of 32 partials.
// ---------------------------------------------------------------------------
__global__ void __launch_bounds__(1024) rank_kernel(float* __restrict__ out)
{
    __shared__ int warp_tot[32][E];   // inclusive warp totals
    __shared__ int warp_off[32][E];   // exclusive warp offsets (global, incl expert base)
    __shared__ int tot[E];

    const int tid  = threadIdx.x;
    const int wid  = tid >> 5;
    const int lane = tid & 31;
    const int sbase = tid * 16;

    // load 16 expert ids (4x int4)
    int le[16];
    const int4* gi = (const int4*)(g_exp + sbase);
#pragma unroll
    for (int q = 0; q < 4; q++) {
        int4 v = gi[q];
        le[q * 4 + 0] = v.x; le[q * 4 + 1] = v.y;
        le[q * 4 + 2] = v.z; le[q * 4 + 3] = v.w;
    }

    int cnt[E];
#pragma unroll
    for (int e = 0; e < E; e++) cnt[e] = 0;
#pragma unroll
    for (int k = 0; k < 16; k++) cnt[le[k]]++;

    // warp inclusive scan of cnt per expert
    int inc[E];
#pragma unroll
    for (int e = 0; e < E; e++) inc[e] = cnt[e];
#pragma unroll
    for (int off = 1; off < 32; off <<= 1) {
#pragma unroll
        for (int e = 0; e < E; e++) {
            int v = __shfl_up_sync(0xffffffffu, inc[e], off);
            if (lane >= off) inc[e] += v;
        }
    }
    if (lane == 31)
#pragma unroll
        for (int e = 0; e < E; e++) warp_tot[wid][e] = inc[e];
    __syncthreads();

    // warp 0: scan the 32 warp totals per expert, compute expert bases
    if (wid == 0) {
        int wv[E];
#pragma unroll
        for (int e = 0; e < E; e++) wv[e] = warp_tot[lane][e];
        int winc[E];
#pragma unroll
        for (int e = 0; e < E; e++) winc[e] = wv[e];
#pragma unroll
        for (int off = 1; off < 32; off <<= 1) {
#pragma unroll
            for (int e = 0; e < E; e++) {
                int v = __shfl_up_sync(0xffffffffu, winc[e], off);
                if (lane >= off) winc[e] += v;
            }
        }
        // expert totals live in lane 31
        int etot[E];
#pragma unroll
        for (int e = 0; e < E; e++)
            etot[e] = __shfl_sync(0xffffffffu, winc[e], 31);
        int base = 0;
#pragma unroll
        for (int e = 0; e < E; e++) {
            warp_off[lane][e] = base + winc[e] - wv[e];  // exclusive + expert base
            base += etot[e];
        }
        if (lane < E) tot[lane] = etot[lane];
    }
    __syncthreads();

    int off[E];
#pragma unroll
    for (int e = 0; e < E; e++)
        off[e] = warp_off[wid][e] + inc[e] - cnt[e];  // global exclusive prefix

    int run[E];
#pragma unroll
    for (int e = 0; e < E; e++) run[e] = 0;

#pragma unroll
    for (int k = 0; k < 16; k++) {
        int slot = sbase + k;
        int e = le[k];
        int pos = off[e] + run[e];
        run[e]++;
        g_pos[slot] = pos;
        out[OFF_IDX + pos] = (float)(slot >> 1);   // scatter_indices
        out[OFF_SC  + pos] = g_prob[slot];         // scores_sorted
    }

    if (tid < E) out[OFF_CNT + tid] = (float)tot[tid];  // num_tokens_per_expert
}

// ---------------------------------------------------------------------------
// Kernel C: scatter copy — read each token row once, write 2 destination rows.
// One block per token; 256 threads; all 4 loads issued before any store.
// ---------------------------------------------------------------------------
__global__ void __launch_bounds__(256) scatter_kernel(
    const float* __restrict__ x, float* __restrict__ out)
{
    const int t = blockIdx.x;
    const int p0 = g_pos[2 * t];
    const int p1 = g_pos[2 * t + 1];
    const float4* __restrict__ src = (const float4*)x + (size_t)t * 1024;
    float4* __restrict__ d0 = (float4*)(out + OFF_XG) + (size_t)p0 * 1024;
    float4* __restrict__ d1 = (float4*)(out + OFF_XG) + (size_t)p1 * 1024;

    const int i = threadIdx.x;
    float4 v0 = src[i];
    float4 v1 = src[i + 256];
    float4 v2 = src[i + 512];
    float4 v3 = src[i + 768];
    d0[i]       = v0;
    d0[i + 256] = v1;
    d0[i + 512] = v2;
    d0[i + 768] = v3;
    d1[i]       = v0;
    d1[i + 256] = v1;
    d1[i + 512] = v2;
    d1[i + 768] = v3;
}

extern "C" void kernel_launch(void* const* d_in, const int* in_sizes, int n_in,
                              void* d_out, int out_size)
{
    const float* x = (const float*)d_in[0];
    const float* W = (const float*)d_in[1];
    // defensive: identify by size (x = 33554432 elems, W = 32768 elems)
    if (n_in >= 2 && in_sizes[0] == E * D && in_sizes[1] == (int)((size_t)T * D)) {
        const float* tmp = x; x = W; W = tmp;
    }
    float* out = (float*)d_out;

    router_scores_kernel<<<T / 16, 256>>>(x, W);
    rank_kernel<<<1, 1024>>>(out);
    scatter_kernel<<<T, 256>>>(x, out);
}

// round 3
// speedup vs baseline: 1.2033x; 1.2033x over previous
#include <cuda_runtime.h>
#include <math.h>

#define T 8192
#define D 4096
#define E 8
#define KSEL 2
#define SLOTS (T * KSEL)

// Output layout (float32, concatenated in reference-return order)
#define OFF_XG  0
#define OFF_CNT 67108864ll   // 16384*4096
#define OFF_IDX 67108872ll
#define OFF_SC  67125256ll

// Scratch (no allocations allowed -> __device__ globals)
__device__ int   g_exp[SLOTS];
__device__ float g_prob[SLOTS];
__device__ int   g_pos[SLOTS];

__device__ __forceinline__ float dot4(float4 a, float4 b) {
    return a.x * b.x + a.y * b.y + a.z * b.z + a.w * b.w;
}

// ---------------------------------------------------------------------------
// Kernel A: router scores + top-2 + softmax.
// Cooperative block: 256 threads = 8 warps, block handles 4 tokens.
// Warp w covers D-slice [w*512, (w+1)*512) -> 128 float4 -> 4 fully unrolled
// chunks of 32 lanes. 16 independent x LDG.128 per lane in flight.
// Cross-warp combine via 1KB smem. grid = T/4 = 2048 blocks.
// ---------------------------------------------------------------------------
__global__ void __launch_bounds__(256) router_scores_kernel(
    const float* __restrict__ x, const float* __restrict__ W)
{
    __shared__ float part[8][4][E];   // [warp][token][expert]
    __shared__ float red[4][E];

    const int w    = threadIdx.x >> 5;
    const int lane = threadIdx.x & 31;
    const int t0   = blockIdx.x * 4;

    const float4* __restrict__ x4 = (const float4*)x;
    const float4* __restrict__ w4 = (const float4*)W;
    const int rs = D / 4;             // 1024 float4 per row
    const int base = w * 128;         // this warp's float4 slice start

    float acc[4][E];
#pragma unroll
    for (int j = 0; j < 4; j++)
#pragma unroll
        for (int e = 0; e < E; e++) acc[j][e] = 0.f;

#pragma unroll
    for (int it = 0; it < 4; it++) {
        const int i = base + it * 32 + lane;
        float4 xv[4];
#pragma unroll
        for (int j = 0; j < 4; j++)
            xv[j] = x4[(size_t)(t0 + j) * rs + i];
#pragma unroll
        for (int e = 0; e < E; e++) {
            float4 wv = w4[e * rs + i];
#pragma unroll
            for (int j = 0; j < 4; j++)
                acc[j][e] += dot4(xv[j], wv);
        }
    }

    // warp tree-reduce all 32 accumulators
#pragma unroll
    for (int off = 16; off > 0; off >>= 1) {
#pragma unroll
        for (int j = 0; j < 4; j++)
#pragma unroll
            for (int e = 0; e < E; e++)
                acc[j][e] += __shfl_xor_sync(0xffffffffu, acc[j][e], off);
    }

    // lane (j*8+e) writes its designated partial (predicated stores, no
    // dynamic register indexing)
#pragma unroll
    for (int j = 0; j < 4; j++)
#pragma unroll
        for (int e = 0; e < E; e++)
            if (lane == j * 8 + e) part[w][j][e] = acc[j][e];
    __syncthreads();

    if (w == 0) {
        // 32 lanes: lane -> (token = lane>>3, expert = lane&7)
        const int tok = lane >> 3;
        const int e   = lane & 7;
        float s = 0.f;
#pragma unroll
        for (int ww = 0; ww < 8; ww++) s += part[ww][tok][e];
        red[tok][e] = s;
        __syncwarp();

        if (lane < 4) {
            const int t = t0 + lane;
            float b0 = -3.4e38f, b1 = -3.4e38f;
            int i0 = 0, i1 = 0;
#pragma unroll
            for (int ee = 0; ee < E; ee++) {
                float sv = red[lane][ee];
                if (sv > b0) { b1 = b0; i1 = i0; b0 = sv; i0 = ee; }
                else if (sv > b1) { b1 = sv; i1 = ee; }
            }
            float ex = expf(b1 - b0);
            float inv = 1.f / (1.f + ex);
            g_exp[2 * t]      = i0;
            g_exp[2 * t + 1]  = i1;
            g_prob[2 * t]     = inv;
            g_prob[2 * t + 1] = ex * inv;
        }
    }
}

// ---------------------------------------------------------------------------
// Kernel B: deterministic per-expert stable ranking.
// Single block, 1024 threads = 32 warps. Per-thread 16-slot histograms,
// warp-level shuffle scan (5 steps), one cross-warp scan of 32 partials.
// ---------------------------------------------------------------------------
__global__ void __launch_bounds__(1024) rank_kernel(float* __restrict__ out)
{
    __shared__ int warp_tot[32][E];
    __shared__ int warp_off[32][E];
    __shared__ int tot[E];

    const int tid  = threadIdx.x;
    const int wid  = tid >> 5;
    const int lane = tid & 31;
    const int sbase = tid * 16;

    int le[16];
    const int4* gi = (const int4*)(g_exp + sbase);
#pragma unroll
    for (int q = 0; q < 4; q++) {
        int4 v = gi[q];
        le[q * 4 + 0] = v.x; le[q * 4 + 1] = v.y;
        le[q * 4 + 2] = v.z; le[q * 4 + 3] = v.w;
    }

    int cnt[E];
#pragma unroll
    for (int e = 0; e < E; e++) cnt[e] = 0;
#pragma unroll
    for (int k = 0; k < 16; k++) cnt[le[k]]++;

    int inc[E];
#pragma unroll
    for (int e = 0; e < E; e++) inc[e] = cnt[e];
#pragma unroll
    for (int off = 1; off < 32; off <<= 1) {
#pragma unroll
        for (int e = 0; e < E; e++) {
            int v = __shfl_up_sync(0xffffffffu, inc[e], off);
            if (lane >= off) inc[e] += v;
        }
    }
    if (lane == 31)
#pragma unroll
        for (int e = 0; e < E; e++) warp_tot[wid][e] = inc[e];
    __syncthreads();

    if (wid == 0) {
        int wv[E];
#pragma unroll
        for (int e = 0; e < E; e++) wv[e] = warp_tot[lane][e];
        int winc[E];
#pragma unroll
        for (int e = 0; e < E; e++) winc[e] = wv[e];
#pragma unroll
        for (int off = 1; off < 32; off <<= 1) {
#pragma unroll
            for (int e = 0; e < E; e++) {
                int v = __shfl_up_sync(0xffffffffu, winc[e], off);
                if (lane >= off) winc[e] += v;
            }
        }
        int etot[E];
#pragma unroll
        for (int e = 0; e < E; e++)
            etot[e] = __shfl_sync(0xffffffffu, winc[e], 31);
        int base = 0;
#pragma unroll
        for (int e = 0; e < E; e++) {
            warp_off[lane][e] = base + winc[e] - wv[e];
            base += etot[e];
        }
        if (lane < E) tot[lane] = etot[lane];
    }
    __syncthreads();

    int off[E];
#pragma unroll
    for (int e = 0; e < E; e++)
        off[e] = warp_off[wid][e] + inc[e] - cnt[e];

    int run[E];
#pragma unroll
    for (int e = 0; e < E; e++) run[e] = 0;

#pragma unroll
    for (int k = 0; k < 16; k++) {
        int slot = sbase + k;
        int e = le[k];
        int pos = off[e] + run[e];
        run[e]++;
        g_pos[slot] = pos;
        out[OFF_IDX + pos] = (float)(slot >> 1);   // scatter_indices
        out[OFF_SC  + pos] = g_prob[slot];         // scores_sorted
    }

    if (tid < E) out[OFF_CNT + tid] = (float)tot[tid];
}

// ---------------------------------------------------------------------------
// Kernel C: scatter copy — read each token row once, write 2 destination rows.
// One block per token; 256 threads; all loads before stores; streaming stores.
// ---------------------------------------------------------------------------
__global__ void __launch_bounds__(256) scatter_kernel(
    const float* __restrict__ x, float* __restrict__ out)
{
    const int t = blockIdx.x;
    const int p0 = g_pos[2 * t];
    const int p1 = g_pos[2 * t + 1];
    const float4* __restrict__ src = (const float4*)x + (size_t)t * 1024;
    float4* __restrict__ d0 = (float4*)(out + OFF_XG) + (size_t)p0 * 1024;
    float4* __restrict__ d1 = (float4*)(out + OFF_XG) + (size_t)p1 * 1024;

    const int i = threadIdx.x;
    float4 v0 = __ldcs(src + i);
    float4 v1 = __ldcs(src + i + 256);
    float4 v2 = __ldcs(src + i + 512);
    float4 v3 = __ldcs(src + i + 768);
    __stcs(d0 + i,       v0);
    __stcs(d0 + i + 256, v1);
    __stcs(d0 + i + 512, v2);
    __stcs(d0 + i + 768, v3);
    __stcs(d1 + i,       v0);
    __stcs(d1 + i + 256, v1);
    __stcs(d1 + i + 512, v2);
    __stcs(d1 + i + 768, v3);
}

extern "C" void kernel_launch(void* const* d_in, const int* in_sizes, int n_in,
                              void* d_out, int out_size)
{
    const float* x = (const float*)d_in[0];
    const float* W = (const float*)d_in[1];
    if (n_in >= 2 && in_sizes[0] == E * D && in_sizes[1] == (int)((size_t)T * D)) {
        const float* tmp = x; x = W; W = tmp;
    }
    float* out = (float*)d_out;

    router_scores_kernel<<<T / 4, 256>>>(x, W);
    rank_kernel<<<1, 1024>>>(out);
    scatter_kernel<<<T, 256>>>(x, out);
}